// round 16
// baseline (speedup 1.0000x reference)
#include <cuda_runtime.h>
#include <math.h>
#include <stdint.h>

#define Bb 8
#define Ss 512
#define Hh 768
#define Ll 12
#define NHh 12
#define HDd 64
#define FFf 3072
#define NCc 6
#define MM (Bb*Ss)          // 4096 rows
#define BHn (Bb*NHh)        // 96

// ---------------- scratch (device globals; no allocs allowed) ----------------
__device__ float g_x[MM*Hh];
__device__ float g_q[MM*Hh];
__device__ float g_k[MM*Hh];
__device__ float g_v[MM*Hh];
__device__ float g_ctx[MM*Hh];
__device__ float g_t[MM*Hh];
__device__ float g_t2[MM*Hh];
__device__ float g_ff[MM*FFf];
__device__ float g_tab[129*HDd];
__device__ float g_avg[Bb*Hh];
__device__ float g_pool[Bb*Hh];
__device__ float g_zero[Hh];                   // zero-initialized, never written
__device__ float g_S[(size_t)BHn*Ss*Ss];       // 100.7 MB attention scores/probs

// ---------------- relative-position sinusoid table [129,64] ----------------
__global__ void tab_init_kernel(float* tab) {
    for (int idx = threadIdx.x; idx < 129*HDd; idx += blockDim.x) {
        int pos = idx / HDd;
        int i   = idx % HDd;
        double expo = (double)(2*(i/2)) / 64.0;
        double ang  = (double)pos * pow(10000.0, -expo);
        tab[idx] = (i % 2 == 0) ? (float)sin(ang) : (float)cos(ang);
    }
}

// ---------------- embedding + LayerNorm ----------------
__global__ __launch_bounds__(256) void embed_ln_kernel(
    const int* __restrict__ ids, const float* __restrict__ we,
    const float* __restrict__ pe, const float* __restrict__ te,
    const float* __restrict__ g, const float* __restrict__ bt,
    float* __restrict__ out)
{
    int r = blockIdx.x;
    int s = r % Ss;
    int id = ids[r];
    int tid = threadIdx.x;
    __shared__ float red[8];
    float v[3];
    #pragma unroll
    for (int j = 0; j < 3; j++) {
        int c = tid + j*256;
        v[j] = we[(size_t)id*Hh + c] + pe[(size_t)s*Hh + c] + te[c];
    }
    float sm = v[0] + v[1] + v[2];
    for (int o = 16; o > 0; o >>= 1) sm += __shfl_xor_sync(0xffffffff, sm, o);
    if ((tid & 31) == 0) red[tid >> 5] = sm;
    __syncthreads();
    if (tid < 8) {
        float t = red[tid];
        for (int o = 4; o > 0; o >>= 1) t += __shfl_xor_sync(0xff, t, o);
        if (tid == 0) red[0] = t;
    }
    __syncthreads();
    float mu = red[0] * (1.0f/768.0f);
    __syncthreads();
    float d0 = v[0]-mu, d1 = v[1]-mu, d2 = v[2]-mu;
    float s2 = d0*d0 + d1*d1 + d2*d2;
    for (int o = 16; o > 0; o >>= 1) s2 += __shfl_xor_sync(0xffffffff, s2, o);
    if ((tid & 31) == 0) red[tid >> 5] = s2;
    __syncthreads();
    if (tid < 8) {
        float t = red[tid];
        for (int o = 4; o > 0; o >>= 1) t += __shfl_xor_sync(0xff, t, o);
        if (tid == 0) red[0] = t;
    }
    __syncthreads();
    float inv = rsqrtf(red[0] * (1.0f/768.0f) + 1e-12f);
    #pragma unroll
    for (int j = 0; j < 3; j++) {
        int c = tid + j*256;
        out[(size_t)r*Hh + c] = (v[j]-mu) * inv * g[c] + bt[c];
    }
}

// ---------------- add-residual (x + t + t2) + LayerNorm (split-K consumer) ----------------
__global__ __launch_bounds__(256) void add_ln3_kernel(
    const float* __restrict__ x, const float* __restrict__ y,
    const float* __restrict__ y2,
    const float* __restrict__ g, const float* __restrict__ bt,
    float* __restrict__ out)
{
    int r = blockIdx.x;
    int tid = threadIdx.x;
    __shared__ float red[8];
    float v[3];
    #pragma unroll
    for (int j = 0; j < 3; j++) {
        int c = tid + j*256;
        v[j] = x[(size_t)r*Hh + c] + (y[(size_t)r*Hh + c] + y2[(size_t)r*Hh + c]);
    }
    float sm = v[0] + v[1] + v[2];
    for (int o = 16; o > 0; o >>= 1) sm += __shfl_xor_sync(0xffffffff, sm, o);
    if ((tid & 31) == 0) red[tid >> 5] = sm;
    __syncthreads();
    if (tid < 8) {
        float t = red[tid];
        for (int o = 4; o > 0; o >>= 1) t += __shfl_xor_sync(0xff, t, o);
        if (tid == 0) red[0] = t;
    }
    __syncthreads();
    float mu = red[0] * (1.0f/768.0f);
    __syncthreads();
    float d0 = v[0]-mu, d1 = v[1]-mu, d2 = v[2]-mu;
    float s2 = d0*d0 + d1*d1 + d2*d2;
    for (int o = 16; o > 0; o >>= 1) s2 += __shfl_xor_sync(0xffffffff, s2, o);
    if ((tid & 31) == 0) red[tid >> 5] = s2;
    __syncthreads();
    if (tid < 8) {
        float t = red[tid];
        for (int o = 4; o > 0; o >>= 1) t += __shfl_xor_sync(0xff, t, o);
        if (tid == 0) red[0] = t;
    }
    __syncthreads();
    float inv = rsqrtf(red[0] * (1.0f/768.0f) + 1e-12f);
    #pragma unroll
    for (int j = 0; j < 3; j++) {
        int c = tid + j*256;
        out[(size_t)r*Hh + c] = (v[j]-mu) * inv * g[c] + bt[c];
    }
}

// ================= TF32 helpers =================
__device__ __forceinline__ uint32_t cvt_tf32(float x) {
    uint32_t u;
    asm("cvt.rna.tf32.f32 %0, %1;" : "=r"(u) : "f"(x));
    return u;
}
__device__ __forceinline__ uint4 cvt4(float4 p) {
    uint4 u;
    u.x = cvt_tf32(p.x); u.y = cvt_tf32(p.y);
    u.z = cvt_tf32(p.z); u.w = cvt_tf32(p.w);
    return u;
}
__device__ __forceinline__ void mma_tf32(float* c, const uint32_t* a, uint32_t b0, uint32_t b1) {
    asm volatile(
        "mma.sync.aligned.m16n8k8.row.col.f32.tf32.tf32.f32 "
        "{%0,%1,%2,%3}, {%4,%5,%6,%7}, {%8,%9}, {%0,%1,%2,%3};"
        : "+f"(c[0]), "+f"(c[1]), "+f"(c[2]), "+f"(c[3])
        : "r"(a[0]), "r"(a[1]), "r"(a[2]), "r"(a[3]), "r"(b0), "r"(b1));
}

// ================= TF32 GEMM: 128x128x16 tiles, mma.m16n8k8 (R10 core + lda param) =================
#define AS_STRIDE 20
#define BS_STRIDE 136
#define AS_BUF 2560
#define BS_BUF 2176

__device__ __forceinline__ void tgemm_body(
    const float* __restrict__ A, const float* __restrict__ W,
    const float* __restrict__ bias, float* __restrict__ C,
    int N, int K, int lda, int act, int m0, int n0, uint32_t* sm)
{
    uint32_t* As = sm;
    uint32_t* Bs = sm + 2*AS_BUF;

    int tid = threadIdx.x;
    int lane = tid & 31, wid = tid >> 5;
    int wr = wid >> 2, wc = wid & 3;
    int g = lane >> 2, tg = lane & 3;

    float acc[4][4][4];
    #pragma unroll
    for (int mf = 0; mf < 4; mf++)
        #pragma unroll
        for (int nf = 0; nf < 4; nf++)
            #pragma unroll
            for (int i = 0; i < 4; i++) acc[mf][nf][i] = 0.0f;

    float4 pa[2], pb[2];
    #pragma unroll
    for (int j = 0; j < 2; j++) {
        int idx = tid + j*256;
        pa[j] = *(const float4*)&A[(size_t)(m0 + (idx>>2))*lda + ((idx&3)<<2)];
        pb[j] = *(const float4*)&W[(size_t)(idx>>5)*N + n0 + ((idx&31)<<2)];
    }
    int buf = 0;
    #pragma unroll
    for (int j = 0; j < 2; j++) {
        int idx = tid + j*256;
        uint32_t* da = As + buf*AS_BUF + (idx>>2)*AS_STRIDE + ((idx&3)<<2);
        da[0]=cvt_tf32(pa[j].x); da[1]=cvt_tf32(pa[j].y); da[2]=cvt_tf32(pa[j].z); da[3]=cvt_tf32(pa[j].w);
        uint32_t* db = Bs + buf*BS_BUF + (idx>>5)*BS_STRIDE + ((idx&31)<<2);
        db[0]=cvt_tf32(pb[j].x); db[1]=cvt_tf32(pb[j].y); db[2]=cvt_tf32(pb[j].z); db[3]=cvt_tf32(pb[j].w);
    }
    __syncthreads();

    int nt = K >> 4;
    for (int t = 0; t < nt; t++) {
        if (t + 1 < nt) {
            int k0 = (t+1) << 4;
            #pragma unroll
            for (int j = 0; j < 2; j++) {
                int idx = tid + j*256;
                pa[j] = *(const float4*)&A[(size_t)(m0 + (idx>>2))*lda + k0 + ((idx&3)<<2)];
                pb[j] = *(const float4*)&W[(size_t)(k0 + (idx>>5))*N + n0 + ((idx&31)<<2)];
            }
        }
        const uint32_t* Ab = As + buf*AS_BUF;
        const uint32_t* Bbp = Bs + buf*BS_BUF;
        #pragma unroll
        for (int k8 = 0; k8 < 2; k8++) {
            int kb = k8 * 8;
            uint32_t af[4][4];
            #pragma unroll
            for (int mf = 0; mf < 4; mf++) {
                int r = wr*64 + mf*16;
                af[mf][0] = Ab[(r+g  )*AS_STRIDE + kb+tg  ];
                af[mf][1] = Ab[(r+g+8)*AS_STRIDE + kb+tg  ];
                af[mf][2] = Ab[(r+g  )*AS_STRIDE + kb+tg+4];
                af[mf][3] = Ab[(r+g+8)*AS_STRIDE + kb+tg+4];
            }
            #pragma unroll
            for (int nf = 0; nf < 4; nf++) {
                int cn = wc*32 + nf*8 + g;
                uint32_t b0 = Bbp[(kb+tg  )*BS_STRIDE + cn];
                uint32_t b1 = Bbp[(kb+tg+4)*BS_STRIDE + cn];
                #pragma unroll
                for (int mf = 0; mf < 4; mf++)
                    mma_tf32(acc[mf][nf], af[mf], b0, b1);
            }
        }
        if (t + 1 < nt) {
            buf ^= 1;
            #pragma unroll
            for (int j = 0; j < 2; j++) {
                int idx = tid + j*256;
                uint32_t* da = As + buf*AS_BUF + (idx>>2)*AS_STRIDE + ((idx&3)<<2);
                da[0]=cvt_tf32(pa[j].x); da[1]=cvt_tf32(pa[j].y); da[2]=cvt_tf32(pa[j].z); da[3]=cvt_tf32(pa[j].w);
                uint32_t* db = Bs + buf*BS_BUF + (idx>>5)*BS_STRIDE + ((idx&31)<<2);
                db[0]=cvt_tf32(pb[j].x); db[1]=cvt_tf32(pb[j].y); db[2]=cvt_tf32(pb[j].z); db[3]=cvt_tf32(pb[j].w);
            }
        }
        __syncthreads();
    }

    #pragma unroll
    for (int mf = 0; mf < 4; mf++) {
        int r0 = m0 + wr*64 + mf*16 + g;
        #pragma unroll
        for (int nf = 0; nf < 4; nf++) {
            int c0 = n0 + wc*32 + nf*8 + tg*2;
            float bb0 = bias[c0], bb1 = bias[c0+1];
            float v00 = acc[mf][nf][0] + bb0;
            float v01 = acc[mf][nf][1] + bb1;
            float v10 = acc[mf][nf][2] + bb0;
            float v11 = acc[mf][nf][3] + bb1;
            if (act) {
                v00 = v00 * normcdff(v00);
                v01 = v01 * normcdff(v01);
                v10 = v10 * normcdff(v10);
                v11 = v11 * normcdff(v11);
            }
            *(float2*)&C[(size_t)r0*N + c0]     = make_float2(v00, v01);
            *(float2*)&C[(size_t)(r0+8)*N + c0] = make_float2(v10, v11);
        }
    }
}

__global__ __launch_bounds__(256) void tgemm_kernel(
    const float* __restrict__ A, const float* __restrict__ W,
    const float* __restrict__ bias, float* __restrict__ C,
    int N, int K, int act)
{
    __shared__ uint32_t sm[2*AS_BUF + 2*BS_BUF];
    tgemm_body(A, W, bias, C, N, K, K, act, blockIdx.y*128, blockIdx.x*128, sm);
}

// split-K=2 variant: blockIdx.z selects K-half; z=0 writes C0 (+bias), z=1 writes C1 (zero bias)
__global__ __launch_bounds__(256) void tgemm_split_kernel(
    const float* __restrict__ A, const float* __restrict__ W,
    const float* __restrict__ bias, const float* __restrict__ zbias,
    float* __restrict__ C0, float* __restrict__ C1,
    int N, int K)
{
    __shared__ uint32_t sm[2*AS_BUF + 2*BS_BUF];
    int z = blockIdx.z;
    int Kh = K >> 1;
    const float* Az = A + (size_t)z * Kh;
    const float* Wz = W + (size_t)z * Kh * N;
    const float* bz = z ? zbias : bias;
    float* Cz = z ? C1 : C0;
    tgemm_body(Az, Wz, bz, Cz, N, Kh, K, 0, blockIdx.y*128, blockIdx.x*128, sm);
}

__global__ __launch_bounds__(256) void tgemm_qkv_kernel(
    const float* __restrict__ A,
    const float* __restrict__ Wq, const float* __restrict__ Wk, const float* __restrict__ Wv,
    const float* __restrict__ bq, const float* __restrict__ bk, const float* __restrict__ bv,
    float* __restrict__ q, float* __restrict__ k, float* __restrict__ v)
{
    __shared__ uint32_t sm[2*AS_BUF + 2*BS_BUF];
    int mat = blockIdx.x / 6;
    int bxx = blockIdx.x % 6;
    const float* W = (mat == 0) ? Wq : (mat == 1) ? Wk : Wv;
    const float* bi = (mat == 0) ? bq : (mat == 1) ? bk : bv;
    float* C = (mat == 0) ? q : (mat == 1) ? k : v;
    tgemm_body(A, W, bi, C, Hh, Hh, Hh, 0, blockIdx.y*128, bxx*128, sm);
}

// ================= fused attention: mma score+ctx, coalesced epilogue, hoisted Q frags =================
#define R1_OFF 0
#define R2_OFF 4608
#define QW_OFF 8960
#define MB_OFF 17408
#define ATT_WORDS 17920
#define ATT_BYTES (ATT_WORDS*4)

__global__ __launch_bounds__(256) void attn_fused_kernel(
    const float* __restrict__ q, const float* __restrict__ k,
    const float* __restrict__ v, const float* __restrict__ tab,
    const int* __restrict__ mask, float* S, float* __restrict__ ctx)
{
    extern __shared__ float sm[];
    float*    R1f = sm + R1_OFF;
    uint32_t* R1u = (uint32_t*)R1f;
    float*    R2f = sm + R2_OFF;
    uint32_t* R2u = (uint32_t*)R2f;
    float*    qw  = sm + QW_OFF;
    float*    mb  = sm + MB_OFF;

    const int b = blockIdx.z, h = blockIdx.y, i0 = blockIdx.x * 64;
    const int tid = threadIdx.x;
    const int lane = tid & 31, wid = tid >> 5;
    const int g = lane >> 2, tg = lane & 3;
    const int tx = tid & 15, ty = tid >> 4;
    const size_t base = ((size_t)b * Ss) * Hh + h * HDd;
    const size_t rbase = ((size_t)(b*NHh + h)) * Ss;

    for (int j = tid; j < Ss; j += 256)
        mb[j] = (1.0f - (float)mask[b*Ss + j]) * -10000.0f;

    // ---- stage Qt [d][i] stride 72 (tf32) ----
    #pragma unroll
    for (int it = 0; it < 4; it++) {
        int i = (tid >> 4) + it*16;
        int d0 = (tid & 15) * 4;
        float4 qv = *(const float4*)&q[base + (size_t)(i0 + i)*Hh + d0];
        uint4 u = cvt4(qv);
        R1u[(d0+0)*72 + i] = u.x;
        R1u[(d0+1)*72 + i] = u.y;
        R1u[(d0+2)*72 + i] = u.z;
        R1u[(d0+3)*72 + i] = u.w;
    }
    __syncthreads();

    // ---- qrel: qw[i][c] = q_i . tab[c], two 64-bin passes (tabT in R2, fp32) ----
    for (int half = 0; half < 2; half++) {
        int cb = half * 64;
        for (int t = tid; t < 64*16; t += 256) {
            int c = t >> 4, d0 = (t & 15) * 4;
            float4 tv = *(const float4*)&tab[(cb + c)*64 + d0];
            #pragma unroll
            for (int w = 0; w < 4; w++)
                R2f[(d0 + w)*68 + c] = (&tv.x)[w];
        }
        __syncthreads();
        float acc[4][4];
        #pragma unroll
        for (int r = 0; r < 4; r++)
            #pragma unroll
            for (int c = 0; c < 4; c++) acc[r][c] = 0.0f;
        #pragma unroll 4
        for (int d = 0; d < 64; d++) {
            float4 a  = *(float4*)&R1f[d*72 + 4*ty];
            float4 bv = *(float4*)&R2f[d*68 + 4*tx];
            float aa[4] = {a.x, a.y, a.z, a.w};
            float bb[4] = {bv.x, bv.y, bv.z, bv.w};
            #pragma unroll
            for (int r = 0; r < 4; r++)
                #pragma unroll
                for (int c = 0; c < 4; c++)
                    acc[r][c] += aa[r] * bb[c];
        }
        #pragma unroll
        for (int ii = 0; ii < 4; ii++)
            *(float4*)&qw[(4*ty + ii)*132 + cb + 4*tx] =
                make_float4(acc[ii][0], acc[ii][1], acc[ii][2], acc[ii][3]);
        __syncthreads();
    }
    {   // bin 128
        float p[4] = {0.f, 0.f, 0.f, 0.f};
        #pragma unroll
        for (int w = 0; w < 4; w++) {
            int d = 4*tx + w;
            float tv = __ldg(&tab[128*64 + d]);
            float4 a = *(float4*)&R1f[d*72 + 4*ty];
            p[0] += a.x*tv; p[1] += a.y*tv; p[2] += a.z*tv; p[3] += a.w*tv;
        }
        #pragma unroll
        for (int o = 8; o > 0; o >>= 1) {
            #pragma unroll
            for (int ii = 0; ii < 4; ii++)
                p[ii] += __shfl_xor_sync(0xffffffff, p[ii], o);
        }
        if (tx == 0) {
            #pragma unroll
            for (int ii = 0; ii < 4; ii++)
                qw[(4*ty + ii)*132 + 128] = p[ii];
        }
    }

    // ---- score phase: S^T tiles = K(64) @ Q^T(64) via mma, 8 tiles ----
    // warps 4x2: wr = wid>>1 (keys, 16 each), wc = wid&1 (queries, 32 each)
    const int wr = wid >> 1, wc = wid & 1;

    // hoist Q-side (B) fragments: tile-invariant across all 8 score tiles
    uint32_t bq0[8][4], bq1[8][4];
    #pragma unroll
    for (int k8 = 0; k8 < 8; k8++) {
        int kb = k8 * 8;
        #pragma unroll
        for (int nf = 0; nf < 4; nf++) {
            int cn = wc*32 + nf*8 + g;
            bq0[k8][nf] = R1u[(kb+tg  )*72 + cn];
            bq1[k8][nf] = R1u[(kb+tg+4)*72 + cn];
        }
    }

    for (int jt = 0; jt < 8; jt++) {
        __syncthreads();
        // stage Ks [j 64][d 68] tf32
        #pragma unroll
        for (int it = 0; it < 4; it++) {
            int j = (tid >> 4) + it*16;
            int d0 = (tid & 15) * 4;
            float4 kv = *(const float4*)&k[base + (size_t)(jt*64 + j)*Hh + d0];
            *(uint4*)&R2u[j*68 + d0] = cvt4(kv);
        }
        __syncthreads();

        float acc[4][4];
        #pragma unroll
        for (int nf = 0; nf < 4; nf++)
            #pragma unroll
            for (int e = 0; e < 4; e++) acc[nf][e] = 0.0f;

        #pragma unroll
        for (int k8 = 0; k8 < 8; k8++) {
            int kb = k8 * 8;
            int r = wr*16;
            uint32_t af[4];
            af[0] = R2u[(r+g  )*68 + kb+tg  ];
            af[1] = R2u[(r+g+8)*68 + kb+tg  ];
            af[2] = R2u[(r+g  )*68 + kb+tg+4];
            af[3] = R2u[(r+g+8)*68 + kb+tg+4];
            #pragma unroll
            for (int nf = 0; nf < 4; nf++)
                mma_tf32(acc[nf], af, bq0[k8][nf], bq1[k8][nf]);
        }
        __syncthreads();   // Ks reads complete; R2 now reused as S-tile [i 64][stride 68]

        // scatter into smem (banks (8*tg+g)%32 distinct), then coalesced write to S
        #pragma unroll
        for (int nf = 0; nf < 4; nf++) {
            #pragma unroll
            for (int e = 0; e < 4; e++) {
                int jloc = wr*16 + g + ((e >> 1) << 3);
                int iloc = wc*32 + nf*8 + tg*2 + (e & 1);
                int jg = jt*64 + jloc;
                int ig = i0 + iloc;
                int c = jg - ig; c = (c < -64) ? -64 : (c > 64 ? 64 : c); c += 64;
                R2f[iloc*68 + jloc] =
                    (acc[nf][e] + qw[iloc*132 + c]) * 0.125f + mb[jg];
            }
        }
        __syncthreads();
        #pragma unroll
        for (int it = 0; it < 4; it++) {
            int row = (tid >> 4) + it*16;
            int c4 = (tid & 15) * 4;
            *(float4*)&S[(rbase + i0 + row)*(size_t)Ss + jt*64 + c4] =
                *(float4*)&R2f[row*68 + c4];
        }
    }
    __syncthreads();

    // ---- softmax + bins into qw; warp per row ----
    {
        int wp = wid;
        for (int rr = wp; rr < 64; rr += 8) {
            int i = i0 + rr;
            float* srow = S + (rbase + i)*(size_t)Ss;
            float4* s4 = (float4*)srow;
            float4 x[4];
            #pragma unroll
            for (int qq = 0; qq < 4; qq++) x[qq] = s4[lane + 32*qq];

            float mx = -1e30f;
            #pragma unroll
            for (int qq = 0; qq < 4; qq++)
                mx = fmaxf(mx, fmaxf(fmaxf(x[qq].x, x[qq].y), fmaxf(x[qq].z, x[qq].w)));
            #pragma unroll
            for (int o = 16; o > 0; o >>= 1) mx = fmaxf(mx, __shfl_xor_sync(0xffffffff, mx, o));

            float sum = 0.0f;
            #pragma unroll
            for (int qq = 0; qq < 4; qq++) {
                x[qq].x = __expf(x[qq].x - mx); sum += x[qq].x;
                x[qq].y = __expf(x[qq].y - mx); sum += x[qq].y;
                x[qq].z = __expf(x[qq].z - mx); sum += x[qq].z;
                x[qq].w = __expf(x[qq].w - mx); sum += x[qq].w;
            }
            #pragma unroll
            for (int o = 16; o > 0; o >>= 1) sum += __shfl_xor_sync(0xffffffff, sum, o);
            float inv = 1.0f / sum;

            float* wrow = &qw[rr*132];
            *(float4*)&wrow[lane*4] = make_float4(0.f,0.f,0.f,0.f);
            if (lane == 0) *(float4*)&wrow[128] = make_float4(0.f,0.f,0.f,0.f);
            __syncwarp();

            float lo = 0.0f, hi = 0.0f;
            #pragma unroll
            for (int qq = 0; qq < 4; qq++) {
                x[qq].x *= inv; x[qq].y *= inv; x[qq].z *= inv; x[qq].w *= inv;
                s4[lane + 32*qq] = x[qq];
                int jb = (lane + 32*qq) * 4;
                #pragma unroll
                for (int w = 0; w < 4; w++) {
                    int d = jb + w - i;
                    float pv = (&x[qq].x)[w];
                    if (d <= -64)      lo += pv;
                    else if (d >= 64)  hi += pv;
                    else               wrow[d + 64] = pv;
                }
            }
            #pragma unroll
            for (int o = 16; o > 0; o >>= 1) {
                lo += __shfl_xor_sync(0xffffffff, lo, o);
                hi += __shfl_xor_sync(0xffffffff, hi, o);
            }
            if (lane == 0) { wrow[0] = lo; wrow[128] = hi; }
        }
    }

    // ---- ctx phase: ctx = P@V (8 tiles) + wbin@tab (3 tiles) via mma ----
    float acc2[4][4];
    #pragma unroll
    for (int nf = 0; nf < 4; nf++)
        #pragma unroll
        for (int e = 0; e < 4; e++) acc2[nf][e] = 0.0f;

    for (int jt = 0; jt < 8; jt++) {
        __syncthreads();
        #pragma unroll
        for (int it = 0; it < 4; it++) {
            int row = (tid >> 4) + it*16;
            int c0 = (tid & 15) * 4;
            float4 pv = *(const float4*)&S[(rbase + i0 + row)*(size_t)Ss + jt*64 + c0];
            *(uint4*)&R2u[row*68 + c0] = cvt4(pv);
            float4 vv = *(const float4*)&v[base + (size_t)(jt*64 + row)*Hh + c0];
            uint4 uv = cvt4(vv);
            R1u[row*72 + c0+0] = uv.x;
            R1u[row*72 + c0+1] = uv.y;
            R1u[row*72 + c0+2] = uv.z;
            R1u[row*72 + c0+3] = uv.w;
        }
        __syncthreads();

        #pragma unroll
        for (int k8 = 0; k8 < 8; k8++) {
            int kb = k8 * 8;
            int r = wr*16;
            uint32_t af[4];
            af[0] = R2u[(r+g  )*68 + kb+tg  ];
            af[1] = R2u[(r+g+8)*68 + kb+tg  ];
            af[2] = R2u[(r+g  )*68 + kb+tg+4];
            af[3] = R2u[(r+g+8)*68 + kb+tg+4];
            #pragma unroll
            for (int nf = 0; nf < 4; nf++) {
                int cn = wc*32 + nf*8 + g;
                uint32_t b0 = R1u[(kb+tg  )*72 + cn];
                uint32_t b1 = R1u[(kb+tg+4)*72 + cn];
                mma_tf32(acc2[nf], af, b0, b1);
            }
        }
    }

    for (int wt = 0; wt < 3; wt++) {
        __syncthreads();
        int c0b = wt * 64;
        #pragma unroll
        for (int it = 0; it < 4; it++) {
            int cc = (tid >> 4) + it*16;
            int d0 = (tid & 15) * 4;
            int c = c0b + cc;
            float4 tv = (c < 129) ? *(const float4*)&tab[c*64 + d0]
                                  : make_float4(0.f,0.f,0.f,0.f);
            uint4 uv = cvt4(tv);
            R1u[cc*72 + d0+0] = uv.x;
            R1u[cc*72 + d0+1] = uv.y;
            R1u[cc*72 + d0+2] = uv.z;
            R1u[cc*72 + d0+3] = uv.w;
        }
        __syncthreads();

        int nsteps = (wt < 2) ? 8 : 1;
        for (int k8 = 0; k8 < nsteps; k8++) {
            int kb = k8 * 8;
            int r = wr*16;
            uint32_t af[4];
            af[0] = cvt_tf32(qw[(r+g  )*132 + c0b + kb+tg  ]);
            af[1] = cvt_tf32(qw[(r+g+8)*132 + c0b + kb+tg  ]);
            af[2] = cvt_tf32(qw[(r+g  )*132 + c0b + kb+tg+4]);
            af[3] = cvt_tf32(qw[(r+g+8)*132 + c0b + kb+tg+4]);
            #pragma unroll
            for (int nf = 0; nf < 4; nf++) {
                int cn = wc*32 + nf*8 + g;
                uint32_t b0 = R1u[(kb+tg  )*72 + cn];
                uint32_t b1 = R1u[(kb+tg+4)*72 + cn];
                mma_tf32(acc2[nf], af, b0, b1);
            }
        }
    }

    #pragma unroll
    for (int nf = 0; nf < 4; nf++) {
        int d0c = wc*32 + nf*8 + tg*2;
        int r0 = i0 + wr*16 + g;
        *(float2*)&ctx[base + (size_t)r0*Hh + d0c]     = make_float2(acc2[nf][0], acc2[nf][1]);
        *(float2*)&ctx[base + (size_t)(r0+8)*Hh + d0c] = make_float2(acc2[nf][2], acc2[nf][3]);
    }
}

// ---------------- head: avg, pooled, classifier ----------------
__global__ void avg_kernel(const float* __restrict__ x, float* __restrict__ avg) {
    int b = blockIdx.x, hcol = threadIdx.x;
    float s = 0.0f;
    for (int ss = 0; ss < Ss; ss++) s += x[((size_t)(b*Ss + ss))*Hh + hcol];
    avg[b*Hh + hcol] = s * (1.0f/512.0f);
}

__global__ __launch_bounds__(128) void pool_kernel(
    const float* __restrict__ x, const float* __restrict__ pw,
    const float* __restrict__ pb, float* __restrict__ pool)
{
    int b = blockIdx.y;
    int o = blockIdx.x*128 + threadIdx.x;
    __shared__ float xb[768];
    for (int j = threadIdx.x; j < 768; j += 128) xb[j] = x[(size_t)(b*Ss)*Hh + j];
    __syncthreads();
    float s = 0.0f;
    for (int hcol = 0; hcol < 768; hcol++) s += xb[hcol]*pw[(size_t)hcol*Hh + o];
    pool[b*Hh + o] = tanhf(s + pb[o]);
}

__global__ void out_kernel(const float* __restrict__ avg, const float* __restrict__ pool,
                           const float* __restrict__ cw, const float* __restrict__ cb,
                           float* __restrict__ out)
{
    int b = blockIdx.x;
    int tid = threadIdx.x;
    int c = tid >> 5, lane = tid & 31;
    if (c >= NCc) return;
    float s = 0.0f;
    for (int t = lane; t < 2*Hh; t += 32) {
        float xv = (t < Hh) ? avg[b*Hh + t] : pool[b*Hh + t - Hh];
        s += xv * cw[(size_t)t*NCc + c];
    }
    for (int o = 16; o > 0; o >>= 1) s += __shfl_xor_sync(0xffffffff, s, o);
    if (lane == 0) out[b*NCc + c] = s + cb[c];
}

// ---------------- launch ----------------
extern "C" void kernel_launch(void* const* d_in, const int* in_sizes, int n_in,
                              void* d_out, int out_size)
{
    const int*   ids   = (const int*)  d_in[0];
    const int*   mask  = (const int*)  d_in[1];
    const float* we    = (const float*)d_in[2];
    const float* pe    = (const float*)d_in[3];
    const float* te    = (const float*)d_in[4];
    const float* lng   = (const float*)d_in[5];
    const float* lnb   = (const float*)d_in[6];
    const float* Wq    = (const float*)d_in[7];
    const float* bq    = (const float*)d_in[8];
    const float* Wk    = (const float*)d_in[9];
    const float* bk    = (const float*)d_in[10];
    const float* Wv    = (const float*)d_in[11];
    const float* bv    = (const float*)d_in[12];
    const float* Wo    = (const float*)d_in[13];
    const float* bo    = (const float*)d_in[14];
    const float* ln1g  = (const float*)d_in[15];
    const float* ln1b  = (const float*)d_in[16];
    const float* W1    = (const float*)d_in[17];
    const float* b1    = (const float*)d_in[18];
    const float* W2    = (const float*)d_in[19];
    const float* b2    = (const float*)d_in[20];
    const float* ln2g  = (const float*)d_in[21];
    const float* ln2b  = (const float*)d_in[22];
    const float* pw    = (const float*)d_in[23];
    const float* pb    = (const float*)d_in[24];
    const float* cw    = (const float*)d_in[25];
    const float* cb    = (const float*)d_in[26];
    float* out = (float*)d_out;

    float *x, *q, *k, *v, *ctx, *t, *t2, *ff, *tab, *avg, *pool, *zero, *S;
    cudaGetSymbolAddress((void**)&x,    g_x);
    cudaGetSymbolAddress((void**)&q,    g_q);
    cudaGetSymbolAddress((void**)&k,    g_k);
    cudaGetSymbolAddress((void**)&v,    g_v);
    cudaGetSymbolAddress((void**)&ctx,  g_ctx);
    cudaGetSymbolAddress((void**)&t,    g_t);
    cudaGetSymbolAddress((void**)&t2,   g_t2);
    cudaGetSymbolAddress((void**)&ff,   g_ff);
    cudaGetSymbolAddress((void**)&tab,  g_tab);
    cudaGetSymbolAddress((void**)&avg,  g_avg);
    cudaGetSymbolAddress((void**)&pool, g_pool);
    cudaGetSymbolAddress((void**)&zero, g_zero);
    cudaGetSymbolAddress((void**)&S,    g_S);

    cudaFuncSetAttribute(attn_fused_kernel, cudaFuncAttributeMaxDynamicSharedMemorySize, ATT_BYTES);

    tab_init_kernel<<<1, 256>>>(tab);
    embed_ln_kernel<<<MM, 256>>>(ids, we, pe, te, lng, lnb, x);

    dim3 gHs(Hh/128, MM/128, 2); // split-K for N=768 GEMMs
    dim3 gF(FFf/128, MM/128);    // (24, 32)
    dim3 gQKV(18, MM/128);
    dim3 gA(Ss/64, NHh, Bb);     // (8, 12, 8)

    for (int l = 0; l < Ll; l++) {
        tgemm_qkv_kernel<<<gQKV, 256>>>(x,
            Wq + (size_t)l*Hh*Hh, Wk + (size_t)l*Hh*Hh, Wv + (size_t)l*Hh*Hh,
            bq + l*Hh, bk + l*Hh, bv + l*Hh, q, k, v);
        attn_fused_kernel<<<gA, 256, ATT_BYTES>>>(q, k, v, tab, mask, S, ctx);
        tgemm_split_kernel<<<gHs, 256>>>(ctx, Wo + (size_t)l*Hh*Hh, bo + l*Hh, zero,
                                         t, t2, Hh, Hh);
        add_ln3_kernel<<<MM, 256>>>(x, t, t2, ln1g + l*Hh, ln1b + l*Hh, x);
        tgemm_kernel<<<gF, 256>>>(x, W1 + (size_t)l*Hh*FFf, b1 + l*FFf, ff, FFf, Hh, 1);
        tgemm_split_kernel<<<gHs, 256>>>(ff, W2 + (size_t)l*FFf*Hh, b2 + l*Hh, zero,
                                         t, t2, Hh, FFf);
        add_ln3_kernel<<<MM, 256>>>(x, t, t2, ln2g + l*Hh, ln2b + l*Hh, x);
    }

    avg_kernel<<<Bb, Hh>>>(x, avg);
    pool_kernel<<<dim3(6, Bb), 128>>>(x, pw, pb, pool);
    out_kernel<<<Bb, 192>>>(avg, pool, cw, cb, out);
}

// round 17
// speedup vs baseline: 1.0411x; 1.0411x over previous
#include <cuda_runtime.h>
#include <math.h>
#include <stdint.h>

#define Bb 8
#define Ss 512
#define Hh 768
#define Ll 12
#define NHh 12
#define HDd 64
#define FFf 3072
#define NCc 6
#define MM (Bb*Ss)          // 4096 rows
#define BHn (Bb*NHh)        // 96

// ---------------- scratch (device globals; no allocs allowed) ----------------
__device__ float g_x[MM*Hh];
__device__ float g_q[MM*Hh];
__device__ float g_k[MM*Hh];
__device__ float g_v[MM*Hh];
__device__ float g_ctx[MM*Hh];
__device__ float g_t[MM*Hh];
__device__ float g_t2[MM*Hh];
__device__ float g_ff[MM*FFf];
__device__ float g_tab[129*HDd];
__device__ float g_avg[Bb*Hh];
__device__ float g_pool[Bb*Hh];
__device__ float g_zero[Hh];                   // zero-initialized, never written
__device__ float g_S[(size_t)BHn*Ss*Ss];       // 100.7 MB attention scores/probs

// ---------------- relative-position sinusoid table [129,64] (parallel) ----------------
__global__ void tab_init_kernel(float* tab) {
    int idx = blockIdx.x * 256 + threadIdx.x;
    if (idx < 129*HDd) {
        int pos = idx / HDd;
        int i   = idx % HDd;
        double expo = (double)(2*(i/2)) / 64.0;
        double ang  = (double)pos * pow(10000.0, -expo);
        tab[idx] = (i % 2 == 0) ? (float)sin(ang) : (float)cos(ang);
    }
}

// ---------------- embedding + LayerNorm ----------------
__global__ __launch_bounds__(256) void embed_ln_kernel(
    const int* __restrict__ ids, const float* __restrict__ we,
    const float* __restrict__ pe, const float* __restrict__ te,
    const float* __restrict__ g, const float* __restrict__ bt,
    float* __restrict__ out)
{
    int r = blockIdx.x;
    int s = r % Ss;
    int id = ids[r];
    int tid = threadIdx.x;
    __shared__ float red[8];
    float v[3];
    #pragma unroll
    for (int j = 0; j < 3; j++) {
        int c = tid + j*256;
        v[j] = we[(size_t)id*Hh + c] + pe[(size_t)s*Hh + c] + te[c];
    }
    float sm = v[0] + v[1] + v[2];
    for (int o = 16; o > 0; o >>= 1) sm += __shfl_xor_sync(0xffffffff, sm, o);
    if ((tid & 31) == 0) red[tid >> 5] = sm;
    __syncthreads();
    if (tid < 8) {
        float t = red[tid];
        for (int o = 4; o > 0; o >>= 1) t += __shfl_xor_sync(0xff, t, o);
        if (tid == 0) red[0] = t;
    }
    __syncthreads();
    float mu = red[0] * (1.0f/768.0f);
    __syncthreads();
    float d0 = v[0]-mu, d1 = v[1]-mu, d2 = v[2]-mu;
    float s2 = d0*d0 + d1*d1 + d2*d2;
    for (int o = 16; o > 0; o >>= 1) s2 += __shfl_xor_sync(0xffffffff, s2, o);
    if ((tid & 31) == 0) red[tid >> 5] = s2;
    __syncthreads();
    if (tid < 8) {
        float t = red[tid];
        for (int o = 4; o > 0; o >>= 1) t += __shfl_xor_sync(0xff, t, o);
        if (tid == 0) red[0] = t;
    }
    __syncthreads();
    float inv = rsqrtf(red[0] * (1.0f/768.0f) + 1e-12f);
    #pragma unroll
    for (int j = 0; j < 3; j++) {
        int c = tid + j*256;
        out[(size_t)r*Hh + c] = (v[j]-mu) * inv * g[c] + bt[c];
    }
}

// ---------------- add-residual (x + t + t2) + LayerNorm (split-K consumer) ----------------
__global__ __launch_bounds__(256) void add_ln3_kernel(
    const float* __restrict__ x, const float* __restrict__ y,
    const float* __restrict__ y2,
    const float* __restrict__ g, const float* __restrict__ bt,
    float* __restrict__ out)
{
    int r = blockIdx.x;
    int tid = threadIdx.x;
    __shared__ float red[8];
    float v[3];
    #pragma unroll
    for (int j = 0; j < 3; j++) {
        int c = tid + j*256;
        v[j] = x[(size_t)r*Hh + c] + (y[(size_t)r*Hh + c] + y2[(size_t)r*Hh + c]);
    }
    float sm = v[0] + v[1] + v[2];
    for (int o = 16; o > 0; o >>= 1) sm += __shfl_xor_sync(0xffffffff, sm, o);
    if ((tid & 31) == 0) red[tid >> 5] = sm;
    __syncthreads();
    if (tid < 8) {
        float t = red[tid];
        for (int o = 4; o > 0; o >>= 1) t += __shfl_xor_sync(0xff, t, o);
        if (tid == 0) red[0] = t;
    }
    __syncthreads();
    float mu = red[0] * (1.0f/768.0f);
    __syncthreads();
    float d0 = v[0]-mu, d1 = v[1]-mu, d2 = v[2]-mu;
    float s2 = d0*d0 + d1*d1 + d2*d2;
    for (int o = 16; o > 0; o >>= 1) s2 += __shfl_xor_sync(0xffffffff, s2, o);
    if ((tid & 31) == 0) red[tid >> 5] = s2;
    __syncthreads();
    if (tid < 8) {
        float t = red[tid];
        for (int o = 4; o > 0; o >>= 1) t += __shfl_xor_sync(0xff, t, o);
        if (tid == 0) red[0] = t;
    }
    __syncthreads();
    float inv = rsqrtf(red[0] * (1.0f/768.0f) + 1e-12f);
    #pragma unroll
    for (int j = 0; j < 3; j++) {
        int c = tid + j*256;
        out[(size_t)r*Hh + c] = (v[j]-mu) * inv * g[c] + bt[c];
    }
}

// ================= TF32 helpers =================
__device__ __forceinline__ uint32_t cvt_tf32(float x) {
    uint32_t u;
    asm("cvt.rna.tf32.f32 %0, %1;" : "=r"(u) : "f"(x));
    return u;
}
__device__ __forceinline__ uint4 cvt4(float4 p) {
    uint4 u;
    u.x = cvt_tf32(p.x); u.y = cvt_tf32(p.y);
    u.z = cvt_tf32(p.z); u.w = cvt_tf32(p.w);
    return u;
}
__device__ __forceinline__ void mma_tf32(float* c, const uint32_t* a, uint32_t b0, uint32_t b1) {
    asm volatile(
        "mma.sync.aligned.m16n8k8.row.col.f32.tf32.tf32.f32 "
        "{%0,%1,%2,%3}, {%4,%5,%6,%7}, {%8,%9}, {%0,%1,%2,%3};"
        : "+f"(c[0]), "+f"(c[1]), "+f"(c[2]), "+f"(c[3])
        : "r"(a[0]), "r"(a[1]), "r"(a[2]), "r"(a[3]), "r"(b0), "r"(b1));
}

// ================= TF32 GEMM: 128x128x16 tiles, mma.m16n8k8 (R10 core + lda param) =================
#define AS_STRIDE 20
#define BS_STRIDE 136
#define AS_BUF 2560
#define BS_BUF 2176

__device__ __forceinline__ void tgemm_body(
    const float* __restrict__ A, const float* __restrict__ W,
    const float* __restrict__ bias, float* __restrict__ C,
    int N, int K, int lda, int act, int m0, int n0, uint32_t* sm)
{
    uint32_t* As = sm;
    uint32_t* Bs = sm + 2*AS_BUF;

    int tid = threadIdx.x;
    int lane = tid & 31, wid = tid >> 5;
    int wr = wid >> 2, wc = wid & 3;
    int g = lane >> 2, tg = lane & 3;

    float acc[4][4][4];
    #pragma unroll
    for (int mf = 0; mf < 4; mf++)
        #pragma unroll
        for (int nf = 0; nf < 4; nf++)
            #pragma unroll
            for (int i = 0; i < 4; i++) acc[mf][nf][i] = 0.0f;

    float4 pa[2], pb[2];
    #pragma unroll
    for (int j = 0; j < 2; j++) {
        int idx = tid + j*256;
        pa[j] = *(const float4*)&A[(size_t)(m0 + (idx>>2))*lda + ((idx&3)<<2)];
        pb[j] = *(const float4*)&W[(size_t)(idx>>5)*N + n0 + ((idx&31)<<2)];
    }
    int buf = 0;
    #pragma unroll
    for (int j = 0; j < 2; j++) {
        int idx = tid + j*256;
        uint32_t* da = As + buf*AS_BUF + (idx>>2)*AS_STRIDE + ((idx&3)<<2);
        da[0]=cvt_tf32(pa[j].x); da[1]=cvt_tf32(pa[j].y); da[2]=cvt_tf32(pa[j].z); da[3]=cvt_tf32(pa[j].w);
        uint32_t* db = Bs + buf*BS_BUF + (idx>>5)*BS_STRIDE + ((idx&31)<<2);
        db[0]=cvt_tf32(pb[j].x); db[1]=cvt_tf32(pb[j].y); db[2]=cvt_tf32(pb[j].z); db[3]=cvt_tf32(pb[j].w);
    }
    __syncthreads();

    int nt = K >> 4;
    for (int t = 0; t < nt; t++) {
        if (t + 1 < nt) {
            int k0 = (t+1) << 4;
            #pragma unroll
            for (int j = 0; j < 2; j++) {
                int idx = tid + j*256;
                pa[j] = *(const float4*)&A[(size_t)(m0 + (idx>>2))*lda + k0 + ((idx&3)<<2)];
                pb[j] = *(const float4*)&W[(size_t)(k0 + (idx>>5))*N + n0 + ((idx&31)<<2)];
            }
        }
        const uint32_t* Ab = As + buf*AS_BUF;
        const uint32_t* Bbp = Bs + buf*BS_BUF;
        #pragma unroll
        for (int k8 = 0; k8 < 2; k8++) {
            int kb = k8 * 8;
            uint32_t af[4][4];
            #pragma unroll
            for (int mf = 0; mf < 4; mf++) {
                int r = wr*64 + mf*16;
                af[mf][0] = Ab[(r+g  )*AS_STRIDE + kb+tg  ];
                af[mf][1] = Ab[(r+g+8)*AS_STRIDE + kb+tg  ];
                af[mf][2] = Ab[(r+g  )*AS_STRIDE + kb+tg+4];
                af[mf][3] = Ab[(r+g+8)*AS_STRIDE + kb+tg+4];
            }
            #pragma unroll
            for (int nf = 0; nf < 4; nf++) {
                int cn = wc*32 + nf*8 + g;
                uint32_t b0 = Bbp[(kb+tg  )*BS_STRIDE + cn];
                uint32_t b1 = Bbp[(kb+tg+4)*BS_STRIDE + cn];
                #pragma unroll
                for (int mf = 0; mf < 4; mf++)
                    mma_tf32(acc[mf][nf], af[mf], b0, b1);
            }
        }
        if (t + 1 < nt) {
            buf ^= 1;
            #pragma unroll
            for (int j = 0; j < 2; j++) {
                int idx = tid + j*256;
                uint32_t* da = As + buf*AS_BUF + (idx>>2)*AS_STRIDE + ((idx&3)<<2);
                da[0]=cvt_tf32(pa[j].x); da[1]=cvt_tf32(pa[j].y); da[2]=cvt_tf32(pa[j].z); da[3]=cvt_tf32(pa[j].w);
                uint32_t* db = Bs + buf*BS_BUF + (idx>>5)*BS_STRIDE + ((idx&31)<<2);
                db[0]=cvt_tf32(pb[j].x); db[1]=cvt_tf32(pb[j].y); db[2]=cvt_tf32(pb[j].z); db[3]=cvt_tf32(pb[j].w);
            }
        }
        __syncthreads();
    }

    #pragma unroll
    for (int mf = 0; mf < 4; mf++) {
        int r0 = m0 + wr*64 + mf*16 + g;
        #pragma unroll
        for (int nf = 0; nf < 4; nf++) {
            int c0 = n0 + wc*32 + nf*8 + tg*2;
            float bb0 = bias[c0], bb1 = bias[c0+1];
            float v00 = acc[mf][nf][0] + bb0;
            float v01 = acc[mf][nf][1] + bb1;
            float v10 = acc[mf][nf][2] + bb0;
            float v11 = acc[mf][nf][3] + bb1;
            if (act) {
                v00 = v00 * normcdff(v00);
                v01 = v01 * normcdff(v01);
                v10 = v10 * normcdff(v10);
                v11 = v11 * normcdff(v11);
            }
            *(float2*)&C[(size_t)r0*N + c0]     = make_float2(v00, v01);
            *(float2*)&C[(size_t)(r0+8)*N + c0] = make_float2(v10, v11);
        }
    }
}

__global__ __launch_bounds__(256) void tgemm_kernel(
    const float* __restrict__ A, const float* __restrict__ W,
    const float* __restrict__ bias, float* __restrict__ C,
    int N, int K, int act)
{
    __shared__ uint32_t sm[2*AS_BUF + 2*BS_BUF];
    tgemm_body(A, W, bias, C, N, K, K, act, blockIdx.y*128, blockIdx.x*128, sm);
}

// split-K=2 variant: blockIdx.z selects K-half; z=0 writes C0 (+bias), z=1 writes C1 (zero bias)
__global__ __launch_bounds__(256) void tgemm_split_kernel(
    const float* __restrict__ A, const float* __restrict__ W,
    const float* __restrict__ bias, const float* __restrict__ zbias,
    float* __restrict__ C0, float* __restrict__ C1,
    int N, int K)
{
    __shared__ uint32_t sm[2*AS_BUF + 2*BS_BUF];
    int z = blockIdx.z;
    int Kh = K >> 1;
    const float* Az = A + (size_t)z * Kh;
    const float* Wz = W + (size_t)z * Kh * N;
    const float* bz = z ? zbias : bias;
    float* Cz = z ? C1 : C0;
    tgemm_body(Az, Wz, bz, Cz, N, Kh, K, 0, blockIdx.y*128, blockIdx.x*128, sm);
}

__global__ __launch_bounds__(256) void tgemm_qkv_kernel(
    const float* __restrict__ A,
    const float* __restrict__ Wq, const float* __restrict__ Wk, const float* __restrict__ Wv,
    const float* __restrict__ bq, const float* __restrict__ bk, const float* __restrict__ bv,
    float* __restrict__ q, float* __restrict__ k, float* __restrict__ v)
{
    __shared__ uint32_t sm[2*AS_BUF + 2*BS_BUF];
    int mat = blockIdx.x / 6;
    int bxx = blockIdx.x % 6;
    const float* W = (mat == 0) ? Wq : (mat == 1) ? Wk : Wv;
    const float* bi = (mat == 0) ? bq : (mat == 1) ? bk : bv;
    float* C = (mat == 0) ? q : (mat == 1) ? k : v;
    tgemm_body(A, W, bi, C, Hh, Hh, Hh, 0, blockIdx.y*128, bxx*128, sm);
}

// ================= fused attention (R15 exact): mma score+ctx, coalesced epilogue =================
#define R1_OFF 0
#define R2_OFF 4608
#define QW_OFF 8960
#define MB_OFF 17408
#define ATT_WORDS 17920
#define ATT_BYTES (ATT_WORDS*4)

__global__ __launch_bounds__(256) void attn_fused_kernel(
    const float* __restrict__ q, const float* __restrict__ k,
    const float* __restrict__ v, const float* __restrict__ tab,
    const int* __restrict__ mask, float* S, float* __restrict__ ctx)
{
    extern __shared__ float sm[];
    float*    R1f = sm + R1_OFF;
    uint32_t* R1u = (uint32_t*)R1f;
    float*    R2f = sm + R2_OFF;
    uint32_t* R2u = (uint32_t*)R2f;
    float*    qw  = sm + QW_OFF;
    float*    mb  = sm + MB_OFF;

    const int b = blockIdx.z, h = blockIdx.y, i0 = blockIdx.x * 64;
    const int tid = threadIdx.x;
    const int lane = tid & 31, wid = tid >> 5;
    const int g = lane >> 2, tg = lane & 3;
    const int tx = tid & 15, ty = tid >> 4;
    const size_t base = ((size_t)b * Ss) * Hh + h * HDd;
    const size_t rbase = ((size_t)(b*NHh + h)) * Ss;

    for (int j = tid; j < Ss; j += 256)
        mb[j] = (1.0f - (float)mask[b*Ss + j]) * -10000.0f;

    // ---- stage Qt [d][i] stride 72 (tf32) ----
    #pragma unroll
    for (int it = 0; it < 4; it++) {
        int i = (tid >> 4) + it*16;
        int d0 = (tid & 15) * 4;
        float4 qv = *(const float4*)&q[base + (size_t)(i0 + i)*Hh + d0];
        uint4 u = cvt4(qv);
        R1u[(d0+0)*72 + i] = u.x;
        R1u[(d0+1)*72 + i] = u.y;
        R1u[(d0+2)*72 + i] = u.z;
        R1u[(d0+3)*72 + i] = u.w;
    }
    __syncthreads();

    // ---- qrel: qw[i][c] = q_i . tab[c], two 64-bin passes (tabT in R2, fp32) ----
    for (int half = 0; half < 2; half++) {
        int cb = half * 64;
        for (int t = tid; t < 64*16; t += 256) {
            int c = t >> 4, d0 = (t & 15) * 4;
            float4 tv = *(const float4*)&tab[(cb + c)*64 + d0];
            #pragma unroll
            for (int w = 0; w < 4; w++)
                R2f[(d0 + w)*68 + c] = (&tv.x)[w];
        }
        __syncthreads();
        float acc[4][4];
        #pragma unroll
        for (int r = 0; r < 4; r++)
            #pragma unroll
            for (int c = 0; c < 4; c++) acc[r][c] = 0.0f;
        #pragma unroll 4
        for (int d = 0; d < 64; d++) {
            float4 a  = *(float4*)&R1f[d*72 + 4*ty];
            float4 bv = *(float4*)&R2f[d*68 + 4*tx];
            float aa[4] = {a.x, a.y, a.z, a.w};
            float bb[4] = {bv.x, bv.y, bv.z, bv.w};
            #pragma unroll
            for (int r = 0; r < 4; r++)
                #pragma unroll
                for (int c = 0; c < 4; c++)
                    acc[r][c] += aa[r] * bb[c];
        }
        #pragma unroll
        for (int ii = 0; ii < 4; ii++)
            *(float4*)&qw[(4*ty + ii)*132 + cb + 4*tx] =
                make_float4(acc[ii][0], acc[ii][1], acc[ii][2], acc[ii][3]);
        __syncthreads();
    }
    {   // bin 128
        float p[4] = {0.f, 0.f, 0.f, 0.f};
        #pragma unroll
        for (int w = 0; w < 4; w++) {
            int d = 4*tx + w;
            float tv = __ldg(&tab[128*64 + d]);
            float4 a = *(float4*)&R1f[d*72 + 4*ty];
            p[0] += a.x*tv; p[1] += a.y*tv; p[2] += a.z*tv; p[3] += a.w*tv;
        }
        #pragma unroll
        for (int o = 8; o > 0; o >>= 1) {
            #pragma unroll
            for (int ii = 0; ii < 4; ii++)
                p[ii] += __shfl_xor_sync(0xffffffff, p[ii], o);
        }
        if (tx == 0) {
            #pragma unroll
            for (int ii = 0; ii < 4; ii++)
                qw[(4*ty + ii)*132 + 128] = p[ii];
        }
    }

    // ---- score phase: S^T tiles = K(64) @ Q^T(64) via mma, 8 tiles ----
    const int wr = wid >> 1, wc = wid & 1;
    for (int jt = 0; jt < 8; jt++) {
        __syncthreads();
        #pragma unroll
        for (int it = 0; it < 4; it++) {
            int j = (tid >> 4) + it*16;
            int d0 = (tid & 15) * 4;
            float4 kv = *(const float4*)&k[base + (size_t)(jt*64 + j)*Hh + d0];
            *(uint4*)&R2u[j*68 + d0] = cvt4(kv);
        }
        __syncthreads();

        float acc[4][4];
        #pragma unroll
        for (int nf = 0; nf < 4; nf++)
            #pragma unroll
            for (int e = 0; e < 4; e++) acc[nf][e] = 0.0f;

        #pragma unroll
        for (int k8 = 0; k8 < 8; k8++) {
            int kb = k8 * 8;
            int r = wr*16;
            uint32_t af[4];
            af[0] = R2u[(r+g  )*68 + kb+tg  ];
            af[1] = R2u[(r+g+8)*68 + kb+tg  ];
            af[2] = R2u[(r+g  )*68 + kb+tg+4];
            af[3] = R2u[(r+g+8)*68 + kb+tg+4];
            #pragma unroll
            for (int nf = 0; nf < 4; nf++) {
                int cn = wc*32 + nf*8 + g;
                uint32_t b0 = R1u[(kb+tg  )*72 + cn];
                uint32_t b1 = R1u[(kb+tg+4)*72 + cn];
                mma_tf32(acc[nf], af, b0, b1);
            }
        }
        __syncthreads();   // Ks reads complete; R2 now reused as S-tile [i 64][stride 68]

        #pragma unroll
        for (int nf = 0; nf < 4; nf++) {
            #pragma unroll
            for (int e = 0; e < 4; e++) {
                int jloc = wr*16 + g + ((e >> 1) << 3);
                int iloc = wc*32 + nf*8 + tg*2 + (e & 1);
                int jg = jt*64 + jloc;
                int ig = i0 + iloc;
                int c = jg - ig; c = (c < -64) ? -64 : (c > 64 ? 64 : c); c += 64;
                R2f[iloc*68 + jloc] =
                    (acc[nf][e] + qw[iloc*132 + c]) * 0.125f + mb[jg];
            }
        }
        __syncthreads();
        #pragma unroll
        for (int it = 0; it < 4; it++) {
            int row = (tid >> 4) + it*16;
            int c4 = (tid & 15) * 4;
            *(float4*)&S[(rbase + i0 + row)*(size_t)Ss + jt*64 + c4] =
                *(float4*)&R2f[row*68 + c4];
        }
    }
    __syncthreads();

    // ---- softmax + bins into qw; warp per row ----
    {
        int wp = wid;
        for (int rr = wp; rr < 64; rr += 8) {
            int i = i0 + rr;
            float* srow = S + (rbase + i)*(size_t)Ss;
            float4* s4 = (float4*)srow;
            float4 x[4];
            #pragma unroll
            for (int qq = 0; qq < 4; qq++) x[qq] = s4[lane + 32*qq];

            float mx = -1e30f;
            #pragma unroll
            for (int qq = 0; qq < 4; qq++)
                mx = fmaxf(mx, fmaxf(fmaxf(x[qq].x, x[qq].y), fmaxf(x[qq].z, x[qq].w)));
            #pragma unroll
            for (int o = 16; o > 0; o >>= 1) mx = fmaxf(mx, __shfl_xor_sync(0xffffffff, mx, o));

            float sum = 0.0f;
            #pragma unroll
            for (int qq = 0; qq < 4; qq++) {
                x[qq].x = __expf(x[qq].x - mx); sum += x[qq].x;
                x[qq].y = __expf(x[qq].y - mx); sum += x[qq].y;
                x[qq].z = __expf(x[qq].z - mx); sum += x[qq].z;
                x[qq].w = __expf(x[qq].w - mx); sum += x[qq].w;
            }
            #pragma unroll
            for (int o = 16; o > 0; o >>= 1) sum += __shfl_xor_sync(0xffffffff, sum, o);
            float inv = 1.0f / sum;

            float* wrow = &qw[rr*132];
            *(float4*)&wrow[lane*4] = make_float4(0.f,0.f,0.f,0.f);
            if (lane == 0) *(float4*)&wrow[128] = make_float4(0.f,0.f,0.f,0.f);
            __syncwarp();

            float lo = 0.0f, hi = 0.0f;
            #pragma unroll
            for (int qq = 0; qq < 4; qq++) {
                x[qq].x *= inv; x[qq].y *= inv; x[qq].z *= inv; x[qq].w *= inv;
                s4[lane + 32*qq] = x[qq];
                int jb = (lane + 32*qq) * 4;
                #pragma unroll
                for (int w = 0; w < 4; w++) {
                    int d = jb + w - i;
                    float pv = (&x[qq].x)[w];
                    if (d <= -64)      lo += pv;
                    else if (d >= 64)  hi += pv;
                    else               wrow[d + 64] = pv;
                }
            }
            #pragma unroll
            for (int o = 16; o > 0; o >>= 1) {
                lo += __shfl_xor_sync(0xffffffff, lo, o);
                hi += __shfl_xor_sync(0xffffffff, hi, o);
            }
            if (lane == 0) { wrow[0] = lo; wrow[128] = hi; }
        }
    }

    // ---- ctx phase: ctx = P@V (8 tiles) + wbin@tab (3 tiles) via mma ----
    float acc2[4][4];
    #pragma unroll
    for (int nf = 0; nf < 4; nf++)
        #pragma unroll
        for (int e = 0; e < 4; e++) acc2[nf][e] = 0.0f;

    for (int jt = 0; jt < 8; jt++) {
        __syncthreads();
        #pragma unroll
        for (int it = 0; it < 4; it++) {
            int row = (tid >> 4) + it*16;
            int c0 = (tid & 15) * 4;
            float4 pv = *(const float4*)&S[(rbase + i0 + row)*(size_t)Ss + jt*64 + c0];
            *(uint4*)&R2u[row*68 + c0] = cvt4(pv);
            float4 vv = *(const float4*)&v[base + (size_t)(jt*64 + row)*Hh + c0];
            uint4 uv = cvt4(vv);
            R1u[row*72 + c0+0] = uv.x;
            R1u[row*72 + c0+1] = uv.y;
            R1u[row*72 + c0+2] = uv.z;
            R1u[row*72 + c0+3] = uv.w;
        }
        __syncthreads();

        #pragma unroll
        for (int k8 = 0; k8 < 8; k8++) {
            int kb = k8 * 8;
            int r = wr*16;
            uint32_t af[4];
            af[0] = R2u[(r+g  )*68 + kb+tg  ];
            af[1] = R2u[(r+g+8)*68 + kb+tg  ];
            af[2] = R2u[(r+g  )*68 + kb+tg+4];
            af[3] = R2u[(r+g+8)*68 + kb+tg+4];
            #pragma unroll
            for (int nf = 0; nf < 4; nf++) {
                int cn = wc*32 + nf*8 + g;
                uint32_t b0 = R1u[(kb+tg  )*72 + cn];
                uint32_t b1 = R1u[(kb+tg+4)*72 + cn];
                mma_tf32(acc2[nf], af, b0, b1);
            }
        }
    }

    for (int wt = 0; wt < 3; wt++) {
        __syncthreads();
        int c0b = wt * 64;
        #pragma unroll
        for (int it = 0; it < 4; it++) {
            int cc = (tid >> 4) + it*16;
            int d0 = (tid & 15) * 4;
            int c = c0b + cc;
            float4 tv = (c < 129) ? *(const float4*)&tab[c*64 + d0]
                                  : make_float4(0.f,0.f,0.f,0.f);
            uint4 uv = cvt4(tv);
            R1u[cc*72 + d0+0] = uv.x;
            R1u[cc*72 + d0+1] = uv.y;
            R1u[cc*72 + d0+2] = uv.z;
            R1u[cc*72 + d0+3] = uv.w;
        }
        __syncthreads();

        int nsteps = (wt < 2) ? 8 : 1;
        for (int k8 = 0; k8 < nsteps; k8++) {
            int kb = k8 * 8;
            int r = wr*16;
            uint32_t af[4];
            af[0] = cvt_tf32(qw[(r+g  )*132 + c0b + kb+tg  ]);
            af[1] = cvt_tf32(qw[(r+g+8)*132 + c0b + kb+tg  ]);
            af[2] = cvt_tf32(qw[(r+g  )*132 + c0b + kb+tg+4]);
            af[3] = cvt_tf32(qw[(r+g+8)*132 + c0b + kb+tg+4]);
            #pragma unroll
            for (int nf = 0; nf < 4; nf++) {
                int cn = wc*32 + nf*8 + g;
                uint32_t b0 = R1u[(kb+tg  )*72 + cn];
                uint32_t b1 = R1u[(kb+tg+4)*72 + cn];
                mma_tf32(acc2[nf], af, b0, b1);
            }
        }
    }

    #pragma unroll
    for (int nf = 0; nf < 4; nf++) {
        int d0c = wc*32 + nf*8 + tg*2;
        int r0 = i0 + wr*16 + g;
        *(float2*)&ctx[base + (size_t)r0*Hh + d0c]     = make_float2(acc2[nf][0], acc2[nf][1]);
        *(float2*)&ctx[base + (size_t)(r0+8)*Hh + d0c] = make_float2(acc2[nf][2], acc2[nf][3]);
    }
}

// ---------------- head: avg (4-way ILP), pooled, classifier ----------------
__global__ void avg_kernel(const float* __restrict__ x, float* __restrict__ avg) {
    int b = blockIdx.x, hcol = threadIdx.x;
    const float* p = x + (size_t)(b*Ss)*Hh + hcol;
    float s0 = 0.f, s1 = 0.f, s2 = 0.f, s3 = 0.f;
    #pragma unroll 4
    for (int ss = 0; ss < Ss; ss += 4) {
        s0 += __ldg(p + (size_t)(ss  )*Hh);
        s1 += __ldg(p + (size_t)(ss+1)*Hh);
        s2 += __ldg(p + (size_t)(ss+2)*Hh);
        s3 += __ldg(p + (size_t)(ss+3)*Hh);
    }
    avg[b*Hh + hcol] = ((s0 + s1) + (s2 + s3)) * (1.0f/512.0f);
}

__global__ __launch_bounds__(128) void pool_kernel(
    const float* __restrict__ x, const float* __restrict__ pw,
    const float* __restrict__ pb, float* __restrict__ pool)
{
    int b = blockIdx.y;
    int o = blockIdx.x*128 + threadIdx.x;
    __shared__ float xb[768];
    for (int j = threadIdx.x; j < 768; j += 128) xb[j] = x[(size_t)(b*Ss)*Hh + j];
    __syncthreads();
    float s = 0.0f;
    for (int hcol = 0; hcol < 768; hcol++) s += xb[hcol]*pw[(size_t)hcol*Hh + o];
    pool[b*Hh + o] = tanhf(s + pb[o]);
}

__global__ void out_kernel(const float* __restrict__ avg, const float* __restrict__ pool,
                           const float* __restrict__ cw, const float* __restrict__ cb,
                           float* __restrict__ out)
{
    int b = blockIdx.x;
    int tid = threadIdx.x;
    int c = tid >> 5, lane = tid & 31;
    if (c >= NCc) return;
    float s = 0.0f;
    for (int t = lane; t < 2*Hh; t += 32) {
        float xv = (t < Hh) ? avg[b*Hh + t] : pool[b*Hh + t - Hh];
        s += xv * cw[(size_t)t*NCc + c];
    }
    for (int o = 16; o > 0; o >>= 1) s += __shfl_xor_sync(0xffffffff, s, o);
    if (lane == 0) out[b*NCc + c] = s + cb[c];
}

// ---------------- launch ----------------
extern "C" void kernel_launch(void* const* d_in, const int* in_sizes, int n_in,
                              void* d_out, int out_size)
{
    const int*   ids   = (const int*)  d_in[0];
    const int*   mask  = (const int*)  d_in[1];
    const float* we    = (const float*)d_in[2];
    const float* pe    = (const float*)d_in[3];
    const float* te    = (const float*)d_in[4];
    const float* lng   = (const float*)d_in[5];
    const float* lnb   = (const float*)d_in[6];
    const float* Wq    = (const float*)d_in[7];
    const float* bq    = (const float*)d_in[8];
    const float* Wk    = (const float*)d_in[9];
    const float* bk    = (const float*)d_in[10];
    const float* Wv    = (const float*)d_in[11];
    const float* bv    = (const float*)d_in[12];
    const float* Wo    = (const float*)d_in[13];
    const float* bo    = (const float*)d_in[14];
    const float* ln1g  = (const float*)d_in[15];
    const float* ln1b  = (const float*)d_in[16];
    const float* W1    = (const float*)d_in[17];
    const float* b1    = (const float*)d_in[18];
    const float* W2    = (const float*)d_in[19];
    const float* b2    = (const float*)d_in[20];
    const float* ln2g  = (const float*)d_in[21];
    const float* ln2b  = (const float*)d_in[22];
    const float* pw    = (const float*)d_in[23];
    const float* pb    = (const float*)d_in[24];
    const float* cw    = (const float*)d_in[25];
    const float* cb    = (const float*)d_in[26];
    float* out = (float*)d_out;

    float *x, *q, *k, *v, *ctx, *t, *t2, *ff, *tab, *avg, *pool, *zero, *S;
    cudaGetSymbolAddress((void**)&x,    g_x);
    cudaGetSymbolAddress((void**)&q,    g_q);
    cudaGetSymbolAddress((void**)&k,    g_k);
    cudaGetSymbolAddress((void**)&v,    g_v);
    cudaGetSymbolAddress((void**)&ctx,  g_ctx);
    cudaGetSymbolAddress((void**)&t,    g_t);
    cudaGetSymbolAddress((void**)&t2,   g_t2);
    cudaGetSymbolAddress((void**)&ff,   g_ff);
    cudaGetSymbolAddress((void**)&tab,  g_tab);
    cudaGetSymbolAddress((void**)&avg,  g_avg);
    cudaGetSymbolAddress((void**)&pool, g_pool);
    cudaGetSymbolAddress((void**)&zero, g_zero);
    cudaGetSymbolAddress((void**)&S,    g_S);

    cudaFuncSetAttribute(attn_fused_kernel, cudaFuncAttributeMaxDynamicSharedMemorySize, ATT_BYTES);

    tab_init_kernel<<<(129*HDd + 255)/256, 256>>>(tab);
    embed_ln_kernel<<<MM, 256>>>(ids, we, pe, te, lng, lnb, x);

    dim3 gHs(Hh/128, MM/128, 2); // split-K for N=768 GEMMs
    dim3 gF(FFf/128, MM/128);    // (24, 32)
    dim3 gQKV(18, MM/128);
    dim3 gA(Ss/64, NHh, Bb);     // (8, 12, 8)

    for (int l = 0; l < Ll; l++) {
        tgemm_qkv_kernel<<<gQKV, 256>>>(x,
            Wq + (size_t)l*Hh*Hh, Wk + (size_t)l*Hh*Hh, Wv + (size_t)l*Hh*Hh,
            bq + l*Hh, bk + l*Hh, bv + l*Hh, q, k, v);
        attn_fused_kernel<<<gA, 256, ATT_BYTES>>>(q, k, v, tab, mask, S, ctx);
        tgemm_split_kernel<<<gHs, 256>>>(ctx, Wo + (size_t)l*Hh*Hh, bo + l*Hh, zero,
                                         t, t2, Hh, Hh);
        add_ln3_kernel<<<MM, 256>>>(x, t, t2, ln1g + l*Hh, ln1b + l*Hh, x);
        tgemm_kernel<<<gF, 256>>>(x, W1 + (size_t)l*Hh*FFf, b1 + l*FFf, ff, FFf, Hh, 1);
        tgemm_split_kernel<<<gHs, 256>>>(ff, W2 + (size_t)l*FFf*Hh, b2 + l*Hh, zero,
                                         t, t2, Hh, FFf);
        add_ln3_kernel<<<MM, 256>>>(x, t, t2, ln2g + l*Hh, ln2b + l*Hh, x);
    }

    avg_kernel<<<Bb, Hh>>>(x, avg);
    pool_kernel<<<dim3(6, Bb), 128>>>(x, pw, pb, pool);
    out_kernel<<<Bb, 192>>>(avg, pool, cw, cb, out);
}